// round 7
// baseline (speedup 1.0000x reference)
#include <cuda_runtime.h>
#include <cuda_bf16.h>
#include <mma.h>
#include <math.h>

using namespace nvcuda;

#define NB   2
#define NN   256
#define NF   64
#define NKF  50
#define NH   4
#define NC   256
#define DCAT 179   // 2F + KF + 1

// scratch (static device memory; allocation-free)
__device__ __nv_bfloat16 g_Uhi[(size_t)NB*NN*NN*NC];  // [bi][j][c'] hi part
__device__ __nv_bfloat16 g_Ulo[(size_t)NB*NN*NN*NC];  // lo part
__device__ __nv_bfloat16 g_Bhi[NC*NC];                // permuted W_xmix hi
__device__ __nv_bfloat16 g_Blo[NC*NC];                // permuted W_xmix lo
__device__ float g_hes[NB*NN*NC];                     // [bi][c] c=f*4+hd

// FFMA-only reciprocal (bit trick + 3 Newton steps, rel err ~1e-12)
__device__ __forceinline__ float frcp_ffma(float x){
    float r = __int_as_float(0x7EF311C3 - __float_as_int(x));
    r = r*(2.f - x*r);
    r = r*(2.f - x*r);
    r = r*(2.f - x*r);
    return r;
}
// silu with 1 MUFU (EX2 inside __expf), reciprocal on fma pipe
__device__ __forceinline__ float siluf(float v){
    const float vc = fmaxf(v, -30.f);
    return v * frcp_ffma(1.f + __expf(-vc));
}
// FFMA-only tanh (XLA rational on [-9,9]); zero MUFU
__device__ __forceinline__ float tanh_ffma(float x){
    float xc = fminf(fmaxf(x, -9.f), 9.f);
    float t  = xc*xc;
    float num = fmaf(t, -2.76076847742355e-16f, 2.00018790482477e-13f);
    num = fmaf(num, t, -8.60467152213735e-11f);
    num = fmaf(num, t,  5.12229709037114e-08f);
    num = fmaf(num, t,  1.48572235717979e-05f);
    num = fmaf(num, t,  6.37261928875436e-04f);
    num = fmaf(num, t,  4.89352455891786e-03f);
    num *= xc;
    float den = fmaf(t, 1.19825839466702e-06f, 1.18534705686654e-04f);
    den = fmaf(den, t, 2.26843463243900e-03f);
    den = fmaf(den, t, 4.89352518554385e-03f);
    return num * frcp_ffma(den);
}
__device__ __forceinline__ void bf16split(float x, __nv_bfloat16& hi, __nv_bfloat16& lo){
    hi = __float2bfloat16(x);
    lo = __float2bfloat16(x - __bfloat162float(hi));
}

// ---------------------------------------------------------------------------
// Prep: split + row-permute W_xmix into bf16 hi/lo (K-row kk <- orig row
// (kk&63)*4 + (kk>>6), matching U's c' = hd*64+f ordering).
// ---------------------------------------------------------------------------
__global__ void k_prep(const float* __restrict__ W_xmix) {
    const int kk = blockIdx.x, c = threadIdx.x;
    const int grow = ((kk & 63) << 2) + (kk >> 6);
    __nv_bfloat16 hi, lo;
    bf16split(W_xmix[grow*NC + c], hi, lo);
    g_Bhi[kk*NC + c] = hi;
    g_Blo[kk*NC + c] = lo;
}

// ---------------------------------------------------------------------------
// Kernel A: edge MLP + semantic attention softmax. One block per (b,i),
// thread j handles pair (i,j). Emits g_Uhi/g_Ulo (bf16) and g_hes (fp32).
// ---------------------------------------------------------------------------
__global__ __launch_bounds__(256, 1) void k_edge(
    const float* __restrict__ h,     const float* __restrict__ x,
    const float* __restrict__ W_in,  const float* __restrict__ b_in,
    const float* __restrict__ means, const float* __restrict__ betas,
    const float* __restrict__ W_o1,  const float* __restrict__ b_o1,
    const float* __restrict__ W_o2,  const float* __restrict__ b_o2,
    const float* __restrict__ W_sem, const float* __restrict__ b_sem)
{
    extern __shared__ __align__(32) float sm[];
    float* sh_h  = sm;                 // 256*65
    float* sWin  = sh_h + NN*65;       // 6400
    float* sWo1  = sWin + 128*NKF;     // 11456
    float* sWo2  = sWo1 + DCAT*64;     // 4096
    float* sWsem = sWo2 + 64*64;       // 256
    float* sbin  = sWsem + 256;
    float* smean = sbin + NKF;
    float* sbeta = smean + NKF;
    float* sbo1  = sbeta + NKF;
    float* sbo2  = sbo1 + 64;
    float* sbsem = sbo2 + 64;
    float* sx    = sbsem + 8;
    float* sLog  = sx + NN*3;
    float* sRed  = sLog + 4*NN;
    // phase-2 aliases (weight region reused after sync)
    float* sHeMat = sWin;              // 256*65
    float* sAttS  = sWin + 16640;      // 256*4

    const int t  = threadIdx.x;
    const int bi = blockIdx.x;
    const int b  = bi >> 8;
    const int i  = bi & 255;

    for (int l = t; l < NN*NF;   l += 256) sh_h[(l>>6)*65 + (l&63)] = h[b*NN*NF + l];
    for (int l = t; l < 128*NKF; l += 256) sWin[l] = W_in[l];
    for (int l = t; l < DCAT*64; l += 256) sWo1[l] = W_o1[l];
    for (int l = t; l < 64*64;   l += 256) sWo2[l] = W_o2[l];
    sWsem[t] = W_sem[t];
    if (t < NKF) { sbin[t]=b_in[t]; smean[t]=means[t]; sbeta[t]=betas[t]; }
    if (t < 64)  { sbo1[t]=b_o1[t]; sbo2[t]=b_o2[t]; }
    if (t < 4)   sbsem[t]=b_sem[t];
    for (int l = t; l < NN*3; l += 256) sx[l] = x[b*NN*3 + l];
    __syncthreads();

    const int j = t;
    const float dx = sx[j*3+0]-sx[i*3+0];
    const float dy = sx[j*3+1]-sx[i*3+1];
    const float dz = sx[j*3+2]-sx[i*3+2];
    const float ss = dx*dx + dy*dy + dz*dz;
    const float d  = sqrtf(fmaxf(ss, 0.f) + 1e-5f);

    float h1[NKF];
    #pragma unroll
    for (int k = 0; k < NKF; k++) h1[k] = sbin[k];
    const float* hj = sh_h + j*65;
    const float* hi = sh_h + i*65;
    for (int f = 0; f < NF; f++) {
        const float vj = hj[f], vi = hi[f];
        const float2* rj = (const float2*)(sWin + f*NKF);
        const float2* ri = (const float2*)(sWin + (64+f)*NKF);
        #pragma unroll
        for (int k2 = 0; k2 < NKF/2; k2++) {
            float2 wj = rj[k2], wi = ri[k2];
            h1[2*k2]   += vj*wj.x + vi*wi.x;
            h1[2*k2+1] += vj*wj.y + vi*wi.y;
        }
    }

    const float em  = __expf(-d);
    const float cut = (d < 5.f) ? 0.5f*(__cosf(d*0.6283185307179586f)+1.f) : 0.f;
    float rh[NKF];
    #pragma unroll
    for (int k = 0; k < NKF; k++) {
        float dm = em - smean[k];
        rh[k] = cut * __expf(-sbeta[k]*dm*dm) * h1[k];
    }

    float tv[64];
    #pragma unroll
    for (int k = 0; k < 64; k++) tv[k] = sbo1[k];
    auto acc_row = [&](float val, const float* row) {
        const float4* r4 = (const float4*)row;
        #pragma unroll
        for (int q = 0; q < 16; q++) {
            float4 w = r4[q];
            tv[4*q+0] += val*w.x; tv[4*q+1] += val*w.y;
            tv[4*q+2] += val*w.z; tv[4*q+3] += val*w.w;
        }
    };
    for (int f = 0; f < 64; f++) acc_row(hj[f], sWo1 + f*64);
    for (int f = 0; f < 64; f++) acc_row(hi[f], sWo1 + (64+f)*64);
    #pragma unroll
    for (int k = 0; k < NKF; k++) acc_row(rh[k], sWo1 + (128+k)*64);
    acc_row(d, sWo1 + 178*64);
    #pragma unroll
    for (int k = 0; k < 64; k++) tv[k] = siluf(tv[k]);

    float he[64];
    #pragma unroll
    for (int k = 0; k < 64; k++) he[k] = sbo2[k];
    #pragma unroll
    for (int c = 0; c < 64; c++) {
        const float val = tv[c];
        const float4* r4 = (const float4*)(sWo2 + c*64);
        #pragma unroll
        for (int q = 0; q < 16; q++) {
            float4 w = r4[q];
            he[4*q+0] += val*w.x; he[4*q+1] += val*w.y;
            he[4*q+2] += val*w.z; he[4*q+3] += val*w.w;
        }
    }

    float l0=sbsem[0], l1=sbsem[1], l2=sbsem[2], l3=sbsem[3];
    #pragma unroll
    for (int f = 0; f < 64; f++) {
        const float v4 = he[f];
        l0 += v4*sWsem[f*4+0]; l1 += v4*sWsem[f*4+1];
        l2 += v4*sWsem[f*4+2]; l3 += v4*sWsem[f*4+3];
    }
    float lg[4] = {l0, l1, l2, l3};
    #pragma unroll
    for (int hd = 0; hd < 4; hd++) {
        float a = lg[hd];
        a = (a > 0.f) ? a : 2.f*(__expf(0.5f*a) - 1.f);
        if (j == i) a -= 1e5f;
        lg[hd] = a;
    }

    __syncthreads();
    #pragma unroll
    for (int f = 0; f < 64; f++) sHeMat[j*65 + f] = he[f];
    #pragma unroll
    for (int hd = 0; hd < 4; hd++) sLog[hd*NN + j] = lg[hd];
    __syncthreads();

    const int wp = t >> 5, lane = t & 31;
    if (wp < 4) {
        float m = -1e30f;
        for (int q = 0; q < 8; q++) m = fmaxf(m, sLog[wp*NN + lane + 32*q]);
        #pragma unroll
        for (int o = 16; o; o >>= 1) m = fmaxf(m, __shfl_xor_sync(~0u, m, o));
        float s = 0.f;
        for (int q = 0; q < 8; q++) s += __expf(sLog[wp*NN + lane + 32*q] - m);
        #pragma unroll
        for (int o = 16; o; o >>= 1) s += __shfl_xor_sync(~0u, s, o);
        if (lane == 0) { sRed[wp*2] = m; sRed[wp*2+1] = frcp_ffma(s); }
    }
    __syncthreads();

    float att4[4];
    #pragma unroll
    for (int hd = 0; hd < 4; hd++) {
        att4[hd] = __expf(sLog[hd*NN + j] - sRed[hd*2]) * sRed[hd*2+1];
        sAttS[j*4 + hd] = att4[hd];
    }
    // write U row (c' = hd*64 + f) as bf16 hi/lo
    {
        __nv_bfloat162* uh = (__nv_bfloat162*)(g_Uhi + ((size_t)bi*NN + j)*NC);
        __nv_bfloat162* ul = (__nv_bfloat162*)(g_Ulo + ((size_t)bi*NN + j)*NC);
        #pragma unroll
        for (int c2 = 0; c2 < 128; c2++) {
            const int i0 = 2*c2;
            const float u0 = att4[(i0+0)>>6] * he[(i0+0)&63];
            const float u1 = att4[(i0+1)>>6] * he[(i0+1)&63];
            __nv_bfloat16 h0, l0b, h1b, l1b;
            bf16split(u0, h0, l0b);
            bf16split(u1, h1b, l1b);
            uh[c2] = __nv_bfloat162(h0, h1b);
            ul[c2] = __nv_bfloat162(l0b, l1b);
        }
    }
    __syncthreads();

    {
        const int f = t >> 2, hd = t & 3;
        float s = 0.f;
        for (int jj = 0; jj < NN; jj++) s += sHeMat[jj*65 + f] * sAttS[jj*4 + hd];
        g_hes[bi*NC + t] = s;
    }
}

// ---------------------------------------------------------------------------
// Kernel B: bf16x2-split wmma GEMM (U @ W') + FFMA-tanh + j-reduction + tail.
// 512 threads / 16 warps: warp tile 16x16. A: 64-row quarters; B: full-K panels.
// ---------------------------------------------------------------------------
#define LDA 264   // bf16 elems
#define LDB 72    // bf16 elems
#define LDD 68    // floats
#define NT  512

__global__ __launch_bounds__(NT, 1) void k_spatial(
    const float* __restrict__ h,    const float* __restrict__ x,
    const float* __restrict__ v,
    const float* __restrict__ W_p1, const float* __restrict__ b_p1,
    const float* __restrict__ W_p2, const float* __restrict__ b_p2,
    const float* __restrict__ W_n1, const float* __restrict__ b_n1,
    const float* __restrict__ W_n2, const float* __restrict__ b_n2,
    const float* __restrict__ W_v1, const float* __restrict__ b_v1,
    const float* __restrict__ W_v2, const float* __restrict__ W_vmix,
    float* __restrict__ out)
{
    extern __shared__ __align__(16) char smraw[];
    __nv_bfloat16* sAhi = (__nv_bfloat16*)smraw;        // 64*264
    __nv_bfloat16* sAlo = sAhi + 64*LDA;
    __nv_bfloat16* sBhi = sAlo + 64*LDA;                // 256*72
    __nv_bfloat16* sBlo = sBhi + 256*LDB;
    float* sD    = (float*)(sBlo + 256*LDB);            // 64*68
    float* sXh   = sD + 64*LDD;        // 1024
    float* sComb = sXh + 1024;         // 768
    float* sHes  = sComb + 768;        // 256
    float* sPart = sHes + 256;         // 8*64*3 = 1536
    float* sHi   = sPart + 1536;       // 64
    float* sT1   = sHi + 64;           // 64
    float* sT2   = sT1 + 64;           // 64
    float* sHn   = sT2 + 64;           // 64
    float* sCn   = sHn + 64;           // 256
    float* sMisc = sCn + 256;          // 16

    const int t  = threadIdx.x;
    const int bi = blockIdx.x;
    const int b  = bi >> 8;
    const int i  = bi & 255;
    const int w  = t >> 5, lane = t & 31;
    const int wr = w & 3;     // M tile (16 rows)
    const int wn = w >> 2;    // N tile (16 cols)

    if (t < 256) sHes[t] = g_hes[bi*NC + t];
    if (t < 64)  sHi[t] = h[(b*NN + i)*64 + t];
    if (t < 256) {
        const int j = t;
        const float xi0 = x[(b*NN+i)*3+0], xi1 = x[(b*NN+i)*3+1], xi2 = x[(b*NN+i)*3+2];
        const float dx = x[(b*NN+j)*3+0]-xi0;
        const float dy = x[(b*NN+j)*3+1]-xi1;
        const float dz = x[(b*NN+j)*3+2]-xi2;
        const float ssq = dx*dx + dy*dy + dz*dz;
        const float dd  = sqrtf(fmaxf(ssq, 0.f) + 1e-5f);
        const float inv = 1.f/(dd + 1e-5f);
        sXh[j*4+0] = dx*inv; sXh[j*4+1] = dy*inv; sXh[j*4+2] = dz*inv;
    }
    __syncthreads();

    for (int qr = 0; qr < 4; qr++) {
        // stage A quarter (64 rows x 256 K) hi/lo: pure 16B copies
        {
            const uint4* ghi = (const uint4*)(g_Uhi + ((size_t)bi*NN + qr*64)*NC);
            const uint4* glo = (const uint4*)(g_Ulo + ((size_t)bi*NN + qr*64)*NC);
            #pragma unroll
            for (int it = 0; it < 4; it++) {
                const int l  = t + it*NT;
                const int jr = l >> 5;     // row 0..63
                const int f8 = l & 31;     // 8-bf16 chunk
                *(uint4*)(sAhi + jr*LDA + f8*8) = ghi[jr*32 + f8];
                *(uint4*)(sAlo + jr*LDA + f8*8) = glo[jr*32 + f8];
            }
        }
        __syncthreads();

        for (int q = 0; q < 4; q++) {
            // stage B panel (256 K x 64 cols) hi/lo
            {
                const uint4* gbh = (const uint4*)g_Bhi;
                const uint4* gbl = (const uint4*)g_Blo;
                #pragma unroll
                for (int it = 0; it < 4; it++) {
                    const int l  = t + it*NT;
                    const int kk = l >> 3;     // K row 0..255
                    const int f8 = l & 7;
                    *(uint4*)(sBhi + kk*LDB + f8*8) = gbh[kk*32 + q*8 + f8];
                    *(uint4*)(sBlo + kk*LDB + f8*8) = gbl[kk*32 + q*8 + f8];
                }
            }
            __syncthreads();

            wmma::fragment<wmma::accumulator,16,16,16,float> acc;
            wmma::fill_fragment(acc, 0.f);

            #pragma unroll 4
            for (int ks = 0; ks < 16; ks++) {
                wmma::fragment<wmma::matrix_a,16,16,16,__nv_bfloat16,wmma::row_major> ah, al;
                wmma::load_matrix_sync(ah, sAhi + (wr*16)*LDA + ks*16, LDA);
                wmma::load_matrix_sync(al, sAlo + (wr*16)*LDA + ks*16, LDA);
                wmma::fragment<wmma::matrix_b,16,16,16,__nv_bfloat16,wmma::row_major> bh, bl;
                wmma::load_matrix_sync(bh, sBhi + (ks*16)*LDB + wn*16, LDB);
                wmma::load_matrix_sync(bl, sBlo + (ks*16)*LDB + wn*16, LDB);
                wmma::mma_sync(acc, ah, bh, acc);
                wmma::mma_sync(acc, ah, bl, acc);
                wmma::mma_sync(acc, al, bh, acc);
            }
            __syncthreads();   // sD free (previous epilogue done)

            wmma::store_matrix_sync(sD + (wr*16)*LDD + wn*16, acc, LDD, wmma::mem_row_major);
            __syncthreads();

            {   // FFMA tanh + xhat-weighted partial reduction (8 groups x 8 rows)
                const int kq = t & 63, grp = t >> 6;
                float p0 = 0.f, p1 = 0.f, p2 = 0.f;
                #pragma unroll
                for (int r = 0; r < 8; r++) {
                    const int jl = grp*8 + r;
                    const int jj = qr*64 + jl;
                    const float c = tanh_ffma(sD[jl*LDD + kq]);
                    p0 += c * sXh[jj*4+0];
                    p1 += c * sXh[jj*4+1];
                    p2 += c * sXh[jj*4+2];
                }
                const int pb = (grp*64 + kq)*3;
                sPart[pb+0] = p0; sPart[pb+1] = p1; sPart[pb+2] = p2;
            }
            __syncthreads();
            if (t < 192) {
                const int kl = t/3, dd = t - kl*3;
                float s = 0.f;
                #pragma unroll
                for (int g = 0; g < 8; g++) s += sPart[(g*64 + kl)*3 + dd];
                s *= (1.f/NN);
                const int ci = (q*64 + kl)*3 + dd;
                if (qr == 0) sComb[ci] = s; else sComb[ci] += s;
            }
            __syncthreads();
        }
    }

    // ---- node tail ----
    if (t < 256) {
        const float c0 = sComb[t*3+0], c1 = sComb[t*3+1], c2 = sComb[t*3+2];
        sCn[t] = c0*c0 + c1*c1 + c2*c2;
    }
    __syncthreads();
    if (t < 64) {
        float a = b_p1[t];
        for (int c = 0; c < 256; c++) a += sCn[c]*W_p1[c*64 + t];
        sT1[t] = siluf(a);
    }
    __syncthreads();
    if (t < 64) {
        float a = b_p2[t];
        for (int c = 0; c < 64; c++) a += sT1[c]*W_p2[c*64 + t];
        sT2[t] = siluf(a);
    }
    __syncthreads();
    if (t < 64) {
        float a = b_n1[t];
        for (int r = 0; r < 64;  r++) a += sHi[r] *W_n1[r*64 + t];
        for (int r = 0; r < 256; r++) a += sHes[r]*W_n1[(64+r)*64 + t];
        for (int r = 0; r < 64;  r++) a += sT2[r] *W_n1[(320+r)*64 + t];
        sT1[t] = siluf(a);
    }
    __syncthreads();
    if (t < 64) {
        float a = b_n2[t];
        for (int c = 0; c < 64; c++) a += sT1[c]*W_n2[c*64 + t];
        const float hn = sHi[t] + siluf(a);
        sHn[t] = hn;
        out[(b*NN + i)*64 + t] = hn;
    }
    __syncthreads();
    if (t < 64) {
        float a = b_v1[t];
        for (int c = 0; c < 64; c++) a += sHn[c]*W_v1[c*64 + t];
        sT1[t] = siluf(a);
    }
    __syncthreads();
    if (w == 0) {
        float s = sT1[lane]*W_v2[lane] + sT1[lane+32]*W_v2[lane+32];
        #pragma unroll
        for (int o = 16; o; o >>= 1) s += __shfl_xor_sync(~0u, s, o);
        if (lane == 0) sMisc[0] = 2.f*frcp_ffma(1.f + __expf(-s));
    }
    if (w >= 1 && w <= 3) {
        const int dd = w - 1;
        float s = 0.f;
        for (int q2 = 0; q2 < 8; q2++)
            s += sComb[(lane + 32*q2)*3 + dd]*W_vmix[lane + 32*q2];
        #pragma unroll
        for (int o = 16; o; o >>= 1) s += __shfl_xor_sync(~0u, s, o);
        if (lane == 0) sMisc[1+dd] = s;
    }
    __syncthreads();
    if (t < 3) {
        const float vn = sMisc[1+t] + sMisc[0]*v[(b*NN+i)*3 + t];
        const float xn = x[(b*NN+i)*3 + t] + vn;
        out[NB*NN*64 + (b*NN+i)*3 + t]           = xn;
        out[NB*NN*64 + NB*NN*3 + (b*NN+i)*3 + t] = vn;
    }
}

// ---------------------------------------------------------------------------
extern "C" void kernel_launch(void* const* d_in, const int* in_sizes, int n_in,
                              void* d_out, int out_size)
{
    const float* h      = (const float*)d_in[0];
    const float* x      = (const float*)d_in[1];
    const float* v      = (const float*)d_in[2];
    const float* W_in   = (const float*)d_in[3];
    const float* b_in   = (const float*)d_in[4];
    const float* means  = (const float*)d_in[5];
    const float* betas  = (const float*)d_in[6];
    const float* W_o1   = (const float*)d_in[7];
    const float* b_o1   = (const float*)d_in[8];
    const float* W_o2   = (const float*)d_in[9];
    const float* b_o2   = (const float*)d_in[10];
    const float* W_sem  = (const float*)d_in[11];
    const float* b_sem  = (const float*)d_in[12];
    const float* W_xmix = (const float*)d_in[13];
    const float* W_p1   = (const float*)d_in[14];
    const float* b_p1   = (const float*)d_in[15];
    const float* W_p2   = (const float*)d_in[16];
    const float* b_p2   = (const float*)d_in[17];
    const float* W_n1   = (const float*)d_in[18];
    const float* b_n1   = (const float*)d_in[19];
    const float* W_n2   = (const float*)d_in[20];
    const float* b_n2   = (const float*)d_in[21];
    const float* W_v1   = (const float*)d_in[22];
    const float* b_v1   = (const float*)d_in[23];
    const float* W_v2   = (const float*)d_in[24];
    const float* W_vmix = (const float*)d_in[25];
    float* out = (float*)d_out;

    const size_t smA = (size_t)(NN*65 + 128*NKF + DCAT*64 + 64*64 + 256
                                + 3*NKF + 2*64 + 8 + NN*3 + 4*NN + 16) * sizeof(float);
    const size_t smB = (size_t)(2*64*LDA + 2*256*LDB) * sizeof(__nv_bfloat16)
                     + (size_t)(64*LDD + 1024 + 768 + 256 + 1536 + 4*64 + 256 + 16) * sizeof(float);

    cudaFuncSetAttribute(k_edge,    cudaFuncAttributeMaxDynamicSharedMemorySize, (int)smA);
    cudaFuncSetAttribute(k_spatial, cudaFuncAttributeMaxDynamicSharedMemorySize, (int)smB);

    k_prep<<<NC, NC>>>(W_xmix);
    k_edge<<<NB*NN, 256, smA>>>(h, x, W_in, b_in, means, betas,
                                W_o1, b_o1, W_o2, b_o2, W_sem, b_sem);
    k_spatial<<<NB*NN, NT, smB>>>(h, x, v, W_p1, b_p1, W_p2, b_p2,
                                  W_n1, b_n1, W_n2, b_n2, W_v1, b_v1,
                                  W_v2, W_vmix, out);
}

// round 9
// speedup vs baseline: 1.1939x; 1.1939x over previous
#include <cuda_runtime.h>
#include <cuda_bf16.h>
#include <mma.h>
#include <math.h>

using namespace nvcuda;

#define NB   2
#define NN   256
#define NF   64
#define NKF  50
#define NH   4
#define NC   256
#define DCAT 179   // 2F + KF + 1

// scratch (static device memory; allocation-free)
__device__ __nv_bfloat16 g_Uhi[(size_t)NB*NN*NN*NC];  // [row=bi*256+j][c'] hi
__device__ __nv_bfloat16 g_Ulo[(size_t)NB*NN*NN*NC];  // lo
__device__ __nv_bfloat16 g_Bhi[NC*NC];                // permuted W_xmix hi [k][n]
__device__ __nv_bfloat16 g_Blo[NC*NC];                // lo
__device__ float g_D[(size_t)NB*NN*NN*NC];            // GEMM output (134MB)
__device__ float g_hes[NB*NN*NC];                     // [bi][c] c=f*4+hd

__device__ __forceinline__ float siluf(float v){ return v / (1.f + __expf(-v)); }
__device__ __forceinline__ float tanhap(float x){
    float y; asm("tanh.approx.f32 %0, %1;" : "=f"(y) : "f"(x)); return y;
}
__device__ __forceinline__ void bf16split(float x, __nv_bfloat16& hi, __nv_bfloat16& lo){
    hi = __float2bfloat16(x);
    lo = __float2bfloat16(x - __bfloat162float(hi));
}

// ---------------------------------------------------------------------------
// Prep: split + row-permute W_xmix into bf16 hi/lo. B[k][n]: k = c' (hd-major),
// original W_xmix row = (k&63)*4 + (k>>6).
// ---------------------------------------------------------------------------
__global__ void k_prep(const float* __restrict__ W_xmix) {
    const int kk = blockIdx.x, c = threadIdx.x;
    const int grow = ((kk & 63) << 2) + (kk >> 6);
    __nv_bfloat16 hi, lo;
    bf16split(W_xmix[grow*NC + c], hi, lo);
    g_Bhi[kk*NC + c] = hi;
    g_Blo[kk*NC + c] = lo;
}

// ---------------------------------------------------------------------------
// Kernel A: edge MLP + semantic attention softmax (R4 version, unchanged).
// ---------------------------------------------------------------------------
__global__ __launch_bounds__(256, 1) void k_edge(
    const float* __restrict__ h,     const float* __restrict__ x,
    const float* __restrict__ W_in,  const float* __restrict__ b_in,
    const float* __restrict__ means, const float* __restrict__ betas,
    const float* __restrict__ W_o1,  const float* __restrict__ b_o1,
    const float* __restrict__ W_o2,  const float* __restrict__ b_o2,
    const float* __restrict__ W_sem, const float* __restrict__ b_sem)
{
    extern __shared__ __align__(32) float sm[];
    float* sh_h  = sm;                 // 256*65
    float* sWin  = sh_h + NN*65;       // 6400
    float* sWo1  = sWin + 128*NKF;     // 11456
    float* sWo2  = sWo1 + DCAT*64;     // 4096
    float* sWsem = sWo2 + 64*64;       // 256
    float* sbin  = sWsem + 256;
    float* smean = sbin + NKF;
    float* sbeta = smean + NKF;
    float* sbo1  = sbeta + NKF;
    float* sbo2  = sbo1 + 64;
    float* sbsem = sbo2 + 64;
    float* sx    = sbsem + 8;
    float* sLog  = sx + NN*3;
    float* sRed  = sLog + 4*NN;
    float* sHeMat = sWin;              // alias after sync
    float* sAttS  = sWin + 16640;

    const int t  = threadIdx.x;
    const int bi = blockIdx.x;
    const int b  = bi >> 8;
    const int i  = bi & 255;

    for (int l = t; l < NN*NF;   l += 256) sh_h[(l>>6)*65 + (l&63)] = h[b*NN*NF + l];
    for (int l = t; l < 128*NKF; l += 256) sWin[l] = W_in[l];
    for (int l = t; l < DCAT*64; l += 256) sWo1[l] = W_o1[l];
    for (int l = t; l < 64*64;   l += 256) sWo2[l] = W_o2[l];
    sWsem[t] = W_sem[t];
    if (t < NKF) { sbin[t]=b_in[t]; smean[t]=means[t]; sbeta[t]=betas[t]; }
    if (t < 64)  { sbo1[t]=b_o1[t]; sbo2[t]=b_o2[t]; }
    if (t < 4)   sbsem[t]=b_sem[t];
    for (int l = t; l < NN*3; l += 256) sx[l] = x[b*NN*3 + l];
    __syncthreads();

    const int j = t;
    const float dx = sx[j*3+0]-sx[i*3+0];
    const float dy = sx[j*3+1]-sx[i*3+1];
    const float dz = sx[j*3+2]-sx[i*3+2];
    const float ss = dx*dx + dy*dy + dz*dz;
    const float d  = sqrtf(fmaxf(ss, 0.f) + 1e-5f);

    float h1[NKF];
    #pragma unroll
    for (int k = 0; k < NKF; k++) h1[k] = sbin[k];
    const float* hj = sh_h + j*65;
    const float* hi = sh_h + i*65;
    for (int f = 0; f < NF; f++) {
        const float vj = hj[f], vi = hi[f];
        const float2* rj = (const float2*)(sWin + f*NKF);
        const float2* ri = (const float2*)(sWin + (64+f)*NKF);
        #pragma unroll
        for (int k2 = 0; k2 < NKF/2; k2++) {
            float2 wj = rj[k2], wi = ri[k2];
            h1[2*k2]   += vj*wj.x + vi*wi.x;
            h1[2*k2+1] += vj*wj.y + vi*wi.y;
        }
    }

    const float em  = __expf(-d);
    const float cut = (d < 5.f) ? 0.5f*(__cosf(d*0.6283185307179586f)+1.f) : 0.f;
    float rh[NKF];
    #pragma unroll
    for (int k = 0; k < NKF; k++) {
        float dm = em - smean[k];
        rh[k] = cut * __expf(-sbeta[k]*dm*dm) * h1[k];
    }

    float tv[64];
    #pragma unroll
    for (int k = 0; k < 64; k++) tv[k] = sbo1[k];
    auto acc_row = [&](float val, const float* row) {
        const float4* r4 = (const float4*)row;
        #pragma unroll
        for (int q = 0; q < 16; q++) {
            float4 w = r4[q];
            tv[4*q+0] += val*w.x; tv[4*q+1] += val*w.y;
            tv[4*q+2] += val*w.z; tv[4*q+3] += val*w.w;
        }
    };
    for (int f = 0; f < 64; f++) acc_row(hj[f], sWo1 + f*64);
    for (int f = 0; f < 64; f++) acc_row(hi[f], sWo1 + (64+f)*64);
    #pragma unroll
    for (int k = 0; k < NKF; k++) acc_row(rh[k], sWo1 + (128+k)*64);
    acc_row(d, sWo1 + 178*64);
    #pragma unroll
    for (int k = 0; k < 64; k++) tv[k] = siluf(tv[k]);

    float he[64];
    #pragma unroll
    for (int k = 0; k < 64; k++) he[k] = sbo2[k];
    #pragma unroll
    for (int c = 0; c < 64; c++) {
        const float val = tv[c];
        const float4* r4 = (const float4*)(sWo2 + c*64);
        #pragma unroll
        for (int q = 0; q < 16; q++) {
            float4 w = r4[q];
            he[4*q+0] += val*w.x; he[4*q+1] += val*w.y;
            he[4*q+2] += val*w.z; he[4*q+3] += val*w.w;
        }
    }

    float l0=sbsem[0], l1=sbsem[1], l2=sbsem[2], l3=sbsem[3];
    #pragma unroll
    for (int f = 0; f < 64; f++) {
        const float v4 = he[f];
        l0 += v4*sWsem[f*4+0]; l1 += v4*sWsem[f*4+1];
        l2 += v4*sWsem[f*4+2]; l3 += v4*sWsem[f*4+3];
    }
    float lg[4] = {l0, l1, l2, l3};
    #pragma unroll
    for (int hd = 0; hd < 4; hd++) {
        float a = lg[hd];
        a = (a > 0.f) ? a : 2.f*(__expf(0.5f*a) - 1.f);
        if (j == i) a -= 1e5f;
        lg[hd] = a;
    }

    __syncthreads();
    #pragma unroll
    for (int f = 0; f < 64; f++) sHeMat[j*65 + f] = he[f];
    #pragma unroll
    for (int hd = 0; hd < 4; hd++) sLog[hd*NN + j] = lg[hd];
    __syncthreads();

    const int wp = t >> 5, lane = t & 31;
    if (wp < 4) {
        float m = -1e30f;
        for (int q = 0; q < 8; q++) m = fmaxf(m, sLog[wp*NN + lane + 32*q]);
        #pragma unroll
        for (int o = 16; o; o >>= 1) m = fmaxf(m, __shfl_xor_sync(~0u, m, o));
        float s = 0.f;
        for (int q = 0; q < 8; q++) s += __expf(sLog[wp*NN + lane + 32*q] - m);
        #pragma unroll
        for (int o = 16; o; o >>= 1) s += __shfl_xor_sync(~0u, s, o);
        if (lane == 0) { sRed[wp*2] = m; sRed[wp*2+1] = s; }
    }
    __syncthreads();

    float att4[4];
    #pragma unroll
    for (int hd = 0; hd < 4; hd++) {
        att4[hd] = __expf(sLog[hd*NN + j] - sRed[hd*2]) / sRed[hd*2+1];
        sAttS[j*4 + hd] = att4[hd];
    }
    {
        __nv_bfloat162* uh = (__nv_bfloat162*)(g_Uhi + ((size_t)bi*NN + j)*NC);
        __nv_bfloat162* ul = (__nv_bfloat162*)(g_Ulo + ((size_t)bi*NN + j)*NC);
        #pragma unroll
        for (int c2 = 0; c2 < 128; c2++) {
            const int i0 = 2*c2;
            const float u0 = att4[(i0+0)>>6] * he[(i0+0)&63];
            const float u1 = att4[(i0+1)>>6] * he[(i0+1)&63];
            __nv_bfloat16 h0, l0b, h1b, l1b;
            bf16split(u0, h0, l0b);
            bf16split(u1, h1b, l1b);
            uh[c2] = __nv_bfloat162(h0, h1b);
            ul[c2] = __nv_bfloat162(l0b, l1b);
        }
    }
    __syncthreads();

    {
        const int f = t >> 2, hd = t & 3;
        float s = 0.f;
        for (int jj = 0; jj < NN; jj++) s += sHeMat[jj*65 + f] * sAttS[jj*4 + hd];
        g_hes[bi*NC + t] = s;
    }
}

// ---------------------------------------------------------------------------
// Kernel B: ONE big GEMM  D[131072,256] = U[131072,256] @ W'[256,256]
// bf16 3-term split, fp32 acc. Block tile 128x128, K-chunks of 64.
// ---------------------------------------------------------------------------
#define GLA 72    // A shared stride (bf16)
#define GLB 136   // B shared stride (bf16)

__global__ __launch_bounds__(256, 2) void k_gemm()
{
    extern __shared__ __align__(16) char gsm[];
    __nv_bfloat16* sAhi = (__nv_bfloat16*)gsm;      // 128*72
    __nv_bfloat16* sAlo = sAhi + 128*GLA;
    __nv_bfloat16* sBhi = sAlo + 128*GLA;           // 64*136
    __nv_bfloat16* sBlo = sBhi + 64*GLB;

    const int t    = threadIdx.x;
    const int mblk = blockIdx.x >> 1;
    const int nblk = blockIdx.x & 1;
    const int w    = t >> 5;
    const int wm   = w & 3;      // M sub-tile (32 rows)
    const int wn2  = w >> 2;     // N sub-tile (64 cols)

    wmma::fragment<wmma::accumulator,16,16,16,float> acc[2][4];
    #pragma unroll
    for (int mi = 0; mi < 2; mi++)
        #pragma unroll
        for (int ni = 0; ni < 4; ni++) wmma::fill_fragment(acc[mi][ni], 0.f);

    for (int kc = 0; kc < 4; kc++) {
        // stage A chunk: 128 rows x 64 K (hi/lo)
        {
            const size_t gb = ((size_t)mblk*128)*NC + kc*64;
            #pragma unroll
            for (int it = 0; it < 4; it++) {
                const int l = t + it*256;
                const int row = l >> 3, c8 = l & 7;
                *(uint4*)(sAhi + row*GLA + c8*8) = *(const uint4*)(g_Uhi + gb + (size_t)row*NC + c8*8);
                *(uint4*)(sAlo + row*GLA + c8*8) = *(const uint4*)(g_Ulo + gb + (size_t)row*NC + c8*8);
            }
        }
        // stage B chunk: 64 K x 128 N (hi/lo)
        {
            const int gb = (kc*64)*NC + nblk*128;
            #pragma unroll
            for (int it = 0; it < 4; it++) {
                const int l = t + it*256;
                const int row = l >> 4, c8 = l & 15;
                *(uint4*)(sBhi + row*GLB + c8*8) = *(const uint4*)(g_Bhi + gb + row*NC + c8*8);
                *(uint4*)(sBlo + row*GLB + c8*8) = *(const uint4*)(g_Blo + gb + row*NC + c8*8);
            }
        }
        __syncthreads();

        #pragma unroll
        for (int ks = 0; ks < 4; ks++) {
            wmma::fragment<wmma::matrix_a,16,16,16,__nv_bfloat16,wmma::row_major> ah[2], al[2];
            #pragma unroll
            for (int mi = 0; mi < 2; mi++) {
                wmma::load_matrix_sync(ah[mi], sAhi + (wm*32 + mi*16)*GLA + ks*16, GLA);
                wmma::load_matrix_sync(al[mi], sAlo + (wm*32 + mi*16)*GLA + ks*16, GLA);
            }
            #pragma unroll
            for (int ni = 0; ni < 4; ni++) {
                wmma::fragment<wmma::matrix_b,16,16,16,__nv_bfloat16,wmma::row_major> bh, bl;
                wmma::load_matrix_sync(bh, sBhi + (ks*16)*GLB + wn2*64 + ni*16, GLB);
                wmma::load_matrix_sync(bl, sBlo + (ks*16)*GLB + wn2*64 + ni*16, GLB);
                #pragma unroll
                for (int mi = 0; mi < 2; mi++) {
                    wmma::mma_sync(acc[mi][ni], ah[mi], bh, acc[mi][ni]);
                    wmma::mma_sync(acc[mi][ni], ah[mi], bl, acc[mi][ni]);
                    wmma::mma_sync(acc[mi][ni], al[mi], bh, acc[mi][ni]);
                }
            }
        }
        __syncthreads();
    }

    #pragma unroll
    for (int mi = 0; mi < 2; mi++)
        #pragma unroll
        for (int ni = 0; ni < 4; ni++) {
            float* dst = g_D + ((size_t)mblk*128 + wm*32 + mi*16)*NC
                             + nblk*128 + wn2*64 + ni*16;
            wmma::store_matrix_sync(dst, acc[mi][ni], NC, wmma::mem_row_major);
        }
}

// ---------------------------------------------------------------------------
// Kernel C: tanh + xhat-weighted j-reduction over D + full node tail.
// One block per (b,i), 256 threads; thread t owns output channel c=t.
// ---------------------------------------------------------------------------
__global__ __launch_bounds__(256, 1) void k_reduce(
    const float* __restrict__ h,    const float* __restrict__ x,
    const float* __restrict__ v,
    const float* __restrict__ W_p1, const float* __restrict__ b_p1,
    const float* __restrict__ W_p2, const float* __restrict__ b_p2,
    const float* __restrict__ W_n1, const float* __restrict__ b_n1,
    const float* __restrict__ W_n2, const float* __restrict__ b_n2,
    const float* __restrict__ W_v1, const float* __restrict__ b_v1,
    const float* __restrict__ W_v2, const float* __restrict__ W_vmix,
    float* __restrict__ out)
{
    extern __shared__ __align__(16) float rsm[];
    float* sStage = rsm;               // 32*256
    float* sXh    = sStage + 32*256;   // 1024
    float* sComb  = sXh + 1024;        // 768
    float* sHes   = sComb + 768;       // 256
    float* sHi    = sHes + 256;        // 64
    float* sT1    = sHi + 64;          // 64
    float* sT2    = sT1 + 64;          // 64
    float* sHn    = sT2 + 64;          // 64
    float* sMisc  = sHn + 64;          // 16
    float* sCn    = sStage;            // alias after staging done

    const int t  = threadIdx.x;
    const int bi = blockIdx.x;
    const int b  = bi >> 8;
    const int i  = bi & 255;
    const int w  = t >> 5, lane = t & 31;

    sHes[t] = g_hes[bi*NC + t];
    if (t < 64) sHi[t] = h[(b*NN + i)*64 + t];
    {
        const int j = t;
        const float xi0 = x[(b*NN+i)*3+0], xi1 = x[(b*NN+i)*3+1], xi2 = x[(b*NN+i)*3+2];
        const float dx = x[(b*NN+j)*3+0]-xi0;
        const float dy = x[(b*NN+j)*3+1]-xi1;
        const float dz = x[(b*NN+j)*3+2]-xi2;
        const float ssq = dx*dx + dy*dy + dz*dz;
        const float dd  = sqrtf(fmaxf(ssq, 0.f) + 1e-5f);
        const float inv = 1.f/(dd + 1e-5f);
        sXh[j*4+0] = dx*inv; sXh[j*4+1] = dy*inv; sXh[j*4+2] = dz*inv;
    }
    __syncthreads();

    float a0 = 0.f, a1 = 0.f, a2 = 0.f;
    for (int tile = 0; tile < 8; tile++) {
        {
            const float4* gd = (const float4*)(g_D + ((size_t)bi*NN + tile*32)*NC);
            #pragma unroll
            for (int it = 0; it < 8; it++) {
                const int l = t + it*256;
                const int row = l >> 6, c4 = l & 63;
                *(float4*)(sStage + row*256 + c4*4) = gd[row*64 + c4];
            }
        }
        __syncthreads();
        #pragma unroll 8
        for (int r = 0; r < 32; r++) {
            const int j = tile*32 + r;
            const float tv = tanhap(sStage[r*256 + t]);
            a0 += tv * sXh[j*4+0];
            a1 += tv * sXh[j*4+1];
            a2 += tv * sXh[j*4+2];
        }
        __syncthreads();
    }
    sComb[t*3+0] = a0*(1.f/NN);
    sComb[t*3+1] = a1*(1.f/NN);
    sComb[t*3+2] = a2*(1.f/NN);
    __syncthreads();

    // ---- node tail ----
    {
        const float c0 = sComb[t*3+0], c1 = sComb[t*3+1], c2 = sComb[t*3+2];
        sCn[t] = c0*c0 + c1*c1 + c2*c2;
    }
    __syncthreads();
    if (t < 64) {
        float a = b_p1[t];
        for (int c = 0; c < 256; c++) a += sCn[c]*W_p1[c*64 + t];
        sT1[t] = siluf(a);
    }
    __syncthreads();
    if (t < 64) {
        float a = b_p2[t];
        for (int c = 0; c < 64; c++) a += sT1[c]*W_p2[c*64 + t];
        sT2[t] = siluf(a);
    }
    __syncthreads();
    if (t < 64) {
        float a = b_n1[t];
        for (int r = 0; r < 64;  r++) a += sHi[r] *W_n1[r*64 + t];
        for (int r = 0; r < 256; r++) a += sHes[r]*W_n1[(64+r)*64 + t];
        for (int r = 0; r < 64;  r++) a += sT2[r] *W_n1[(320+r)*64 + t];
        sT1[t] = siluf(a);
    }
    __syncthreads();
    if (t < 64) {
        float a = b_n2[t];
        for (int c = 0; c < 64; c++) a += sT1[c]*W_n2[c*64 + t];
        const float hn = sHi[t] + siluf(a);
        sHn[t] = hn;
        out[(b*NN + i)*64 + t] = hn;
    }
    __syncthreads();
    if (t < 64) {
        float a = b_v1[t];
        for (int c = 0; c < 64; c++) a += sHn[c]*W_v1[c*64 + t];
        sT1[t] = siluf(a);
    }
    __syncthreads();
    if (w == 0) {
        float s = sT1[lane]*W_v2[lane] + sT1[lane+32]*W_v2[lane+32];
        #pragma unroll
        for (int o = 16; o; o >>= 1) s += __shfl_xor_sync(~0u, s, o);
        if (lane == 0) sMisc[0] = 2.f/(1.f + __expf(-s));
    }
    if (w >= 1 && w <= 3) {
        const int dd = w - 1;
        float s = 0.f;
        for (int q2 = 0; q2 < 8; q2++)
            s += sComb[(lane + 32*q2)*3 + dd]*W_vmix[lane + 32*q2];
        #pragma unroll
        for (int o = 16; o; o >>= 1) s += __shfl_xor_sync(~0u, s, o);
        if (lane == 0) sMisc[1+dd] = s;
    }
    __syncthreads();
    if (t < 3) {
        const float vn = sMisc[1+t] + sMisc[0]*v[(b*NN+i)*3 + t];
        const float xn = x[(b*NN+i)*3 + t] + vn;
        out[NB*NN*64 + (b*NN+i)*3 + t]           = xn;
        out[NB*NN*64 + NB*NN*3 + (b*NN+i)*3 + t] = vn;
    }
}

// ---------------------------------------------------------------------------
extern "C" void kernel_launch(void* const* d_in, const int* in_sizes, int n_in,
                              void* d_out, int out_size)
{
    const float* h      = (const float*)d_in[0];
    const float* x      = (const float*)d_in[1];
    const float* v      = (const float*)d_in[2];
    const float* W_in   = (const float*)d_in[3];
    const float* b_in   = (const float*)d_in[4];
    const float* means  = (const float*)d_in[5];
    const float* betas  = (const float*)d_in[6];
    const float* W_o1   = (const float*)d_in[7];
    const float* b_o1   = (const float*)d_in[8];
    const float* W_o2   = (const float*)d_in[9];
    const float* b_o2   = (const float*)d_in[10];
    const float* W_sem  = (const float*)d_in[11];
    const float* b_sem  = (const float*)d_in[12];
    const float* W_xmix = (const float*)d_in[13];
    const float* W_p1   = (const float*)d_in[14];
    const float* b_p1   = (const float*)d_in[15];
    const float* W_p2   = (const float*)d_in[16];
    const float* b_p2   = (const float*)d_in[17];
    const float* W_n1   = (const float*)d_in[18];
    const float* b_n1   = (const float*)d_in[19];
    const float* W_n2   = (const float*)d_in[20];
    const float* b_n2   = (const float*)d_in[21];
    const float* W_v1   = (const float*)d_in[22];
    const float* b_v1   = (const float*)d_in[23];
    const float* W_v2   = (const float*)d_in[24];
    const float* W_vmix = (const float*)d_in[25];
    float* out = (float*)d_out;

    const size_t smA = (size_t)(NN*65 + 128*NKF + DCAT*64 + 64*64 + 256
                                + 3*NKF + 2*64 + 8 + NN*3 + 4*NN + 16) * sizeof(float);
    const size_t smG = (size_t)(2*128*GLA + 2*64*GLB) * sizeof(__nv_bfloat16);
    const size_t smR = (size_t)(32*256 + 1024 + 768 + 256 + 4*64 + 16) * sizeof(float);

    cudaFuncSetAttribute(k_edge,   cudaFuncAttributeMaxDynamicSharedMemorySize, (int)smA);
    cudaFuncSetAttribute(k_gemm,   cudaFuncAttributeMaxDynamicSharedMemorySize, (int)smG);
    cudaFuncSetAttribute(k_reduce, cudaFuncAttributeMaxDynamicSharedMemorySize, (int)smR);

    k_prep<<<NC, NC>>>(W_xmix);
    k_edge<<<NB*NN, 256, smA>>>(h, x, W_in, b_in, means, betas,
                                W_o1, b_o1, W_o2, b_o2, W_sem, b_sem);
    k_gemm<<<2048, 256, smG>>>();
    k_reduce<<<NB*NN, 256, smR>>>(h, x, v, W_p1, b_p1, W_p2, b_p2,
                                  W_n1, b_n1, W_n2, b_n2, W_v1, b_v1,
                                  W_v2, W_vmix, out);
}